// round 5
// baseline (speedup 1.0000x reference)
#include <cuda_runtime.h>

#define D 8
#define NTOT 1024
#define BX 32
#define BY 4
#define NPAIR 2   // 4 outputs per thread as 2 f32x2 pairs

typedef unsigned long long u64;

__device__ __forceinline__ u64 pack2(float lo, float hi) {
    u64 r; asm("mov.b64 %0, {%1,%2};" : "=l"(r) : "f"(lo), "f"(hi)); return r;
}
__device__ __forceinline__ void unpack2(u64 v, float& lo, float& hi) {
    asm("mov.b64 {%0,%1}, %2;" : "=f"(lo), "=f"(hi) : "l"(v));
}
__device__ __forceinline__ u64 fma2(u64 a, u64 b, u64 c) {
    u64 d; asm("fma.rn.f32x2 %0, %1, %2, %3;" : "=l"(d) : "l"(a), "l"(b), "l"(c)); return d;
}
__device__ __forceinline__ u64 mul2(u64 a, u64 b) {
    u64 d; asm("mul.rn.f32x2 %0, %1, %2;" : "=l"(d) : "l"(a), "l"(b)); return d;
}
__device__ __forceinline__ u64 add2(u64 a, u64 b) {
    u64 d; asm("add.rn.f32x2 %0, %1, %2;" : "=l"(d) : "l"(a), "l"(b)); return d;
}
__device__ __forceinline__ float ex2f(float x) {
    float r; asm("ex2.approx.ftz.f32 %0, %1;" : "=f"(r) : "f"(x)); return r;
}
__device__ __forceinline__ float frcp(float x) {
    float r; asm("rcp.approx.ftz.f32 %0, %1;" : "=f"(r) : "f"(x)); return r;
}
__device__ __forceinline__ u64 lo4(float4 v) { return pack2(v.x, v.y); }
__device__ __forceinline__ u64 hi4(float4 v) { return pack2(v.z, v.w); }

// All broadcast constants stored as DUPLICATED pairs: one float4 = two f32x2
// broadcast operands. sigma[0] is pre-folded into AB/An/q0/q1.
// Diagonal correction uses the exact algebraic collapse:
//   poly - tl^2 (1/tl - dd)(l - dd) == 2 - 4*tl*dd
__global__ __launch_bounds__(BX * BY, 6)
void taylor_rbf_fused(const float* __restrict__ x1,
                      const float* __restrict__ x2,
                      const float* __restrict__ L,
                      const float* __restrict__ sigma,
                      float* __restrict__ out) {
    __shared__ float4 sAB4[32];   // [j*4+cp]: s0*cf_j*M (dup pairs, c = 2cp, 2cp+1)
    __shared__ float4 sAn4[32];   // [j*4+cp]: -s0*cf_j*M^2
    __shared__ float4 sI4[32];    // [a*4+kp]: inv2[a][k] * (-0.5*log2 e)
    __shared__ float4 sQ4[D];     // [d]: {q0,q0,q1,q1}  q0=2*s0*cf, q1=-4*s0*cf*tl
    __shared__ float2 sLJ[D];     // lij2_j (duplicated)
    __shared__ float2 sx2[D][NPAIR][BX];

    const int tx = threadIdx.x, ty = threadIdx.y;
    const int tid = ty * BX + tx;

    // ---- per-block constant precompute ----
    if (tid < 64) {
        const int c = tid >> 3, j = tid & 7;
        float s0  = sigma[0];
        float Ljc = L[j * D + c];
        float L0c = L[c];
        float i0c = frcp(L0c * L0c);
        float ijc = frcp(Ljc * Ljc);
        float M   = i0c + ijc;
        float l0j = L[j];
        float lij2 = l0j * l0j;
        float cf  = s0 * sigma[j] * frcp(lij2 * lij2);
        float AB  = cf * M;
        float An  = -AB * M;
        const int fo = j * 16 + (c >> 1) * 4 + (c & 1) * 2;
        float* pAB = (float*)sAB4; pAB[fo] = AB; pAB[fo + 1] = AB;
        float* pAn = (float*)sAn4; pAn[fo] = An; pAn[fo + 1] = An;
        // exp table, reusing (a,k) = (c,j)
        float Lak = L[c * D + j];
        float v = -0.72134752044448170368f * frcp(Lak * Lak);
        const int fi = c * 16 + (j >> 1) * 4 + (j & 1) * 2;
        float* pI = (float*)sI4; pI[fi] = v; pI[fi + 1] = v;
    } else if (tid < 72) {
        const int d = tid - 64;
        float s0 = sigma[0];
        float l0 = L[d];
        float lij2 = l0 * l0;
        float Ldd = L[d * D + d];
        float idd = frcp(Ldd * Ldd);
        float i0d = frcp(lij2);
        float tl  = i0d + idd;
        float cf  = s0 * sigma[d] * frcp(lij2 * lij2);
        float q0  = 2.0f * cf;
        float q1  = -4.0f * cf * tl;
        sQ4[d] = make_float4(q0, q0, q1, q1);
        sLJ[d] = make_float2(lij2, lij2);
    }

    // ---- stage x2 tile: (m, m+32) packed into one float2 ----
    const int m0 = blockIdx.x * (BX * 2 * NPAIR);   // 128 m per block
    {
        const int r = tid;
        const int p = r >> 6;
        const int half = (r >> 5) & 1;
        const int t = r & 31;
        const float* src = x2 + (m0 + r) * D;
        #pragma unroll
        for (int k = 0; k < D; k++) {
            float* dst = (float*)&sx2[k][p][t] + half;
            *dst = src[k];
        }
    }

    const int n = blockIdx.y * BY + ty;
    float a1s[D];
    #pragma unroll
    for (int k = 0; k < D; k++) a1s[k] = x1[n * D + k];

    __syncthreads();

    const u64 NEG1 = pack2(-1.0f, -1.0f);

    // diff^2, packed over the m-pair
    u64 d2[NPAIR][D];
    #pragma unroll
    for (int k = 0; k < D; k++) {
        u64 a1 = pack2(a1s[k], a1s[k]);
        #pragma unroll
        for (int p = 0; p < NPAIR; p++) {
            u64 xp = *(const u64*)&sx2[k][p][tx];
            u64 dd = fma2(xp, NEG1, a1);
            d2[p][k] = mul2(dd, dd);
        }
    }

    // e[p][a] = exp(-0.5 * <d2, inv2[a,:]>) via pre-scaled rows + ex2
    u64 e[NPAIR][D];
    #pragma unroll
    for (int a = 0; a < D; a++) {
        float4 q0 = sI4[a * 4 + 0];
        float4 q1 = sI4[a * 4 + 1];
        float4 q2 = sI4[a * 4 + 2];
        float4 q3 = sI4[a * 4 + 3];
        u64 r0 = lo4(q0), r1 = hi4(q0), r2 = lo4(q1), r3 = hi4(q1);
        u64 r4 = lo4(q2), r5 = hi4(q2), r6 = lo4(q3), r7 = hi4(q3);
        #pragma unroll
        for (int p = 0; p < NPAIR; p++) {
            u64 s0 = mul2(d2[p][0], r0);
            u64 s1 = mul2(d2[p][1], r1);
            s0 = fma2(d2[p][2], r2, s0);
            s1 = fma2(d2[p][3], r3, s1);
            s0 = fma2(d2[p][4], r4, s0);
            s1 = fma2(d2[p][5], r5, s1);
            s0 = fma2(d2[p][6], r6, s0);
            s1 = fma2(d2[p][7], r7, s1);
            u64 s = add2(s0, s1);
            float lo, hi; unpack2(s, lo, hi);
            e[p][a] = pack2(ex2f(lo), ex2f(hi));
        }
    }

    u64 tot[NPAIR], totD[NPAIR];
    #pragma unroll
    for (int p = 0; p < NPAIR; p++) { tot[p] = pack2(0.f, 0.f); totD[p] = pack2(0.f, 0.f); }

    // one pass over j: double-sum + collapsed diagonal correction
    #pragma unroll
    for (int j = 0; j < D; j++) {
        u64 in0[NPAIR], in1[NPAIR];
        #pragma unroll
        for (int p = 0; p < NPAIR; p++) { in0[p] = pack2(0.f, 0.f); in1[p] = pack2(0.f, 0.f); }
        #pragma unroll
        for (int cp = 0; cp < 4; cp++) {
            float4 ab = sAB4[j * 4 + cp];
            float4 an = sAn4[j * 4 + cp];
            u64 AB0 = lo4(ab), AB1 = hi4(ab);
            u64 An0 = lo4(an), An1 = hi4(an);
            const int c0 = 2 * cp, c1 = 2 * cp + 1;
            #pragma unroll
            for (int p = 0; p < NPAIR; p++) {
                u64 t0 = fma2(An0, d2[p][c0], AB0);
                in0[p] = fma2(t0, e[p][c0], in0[p]);
                u64 t1 = fma2(An1, d2[p][c1], AB1);
                in1[p] = fma2(t1, e[p][c1], in1[p]);
            }
        }
        u64 ljp = *(const u64*)&sLJ[j];
        float4 qd = sQ4[j];
        u64 q0p = lo4(qd), q1p = hi4(qd);
        #pragma unroll
        for (int p = 0; p < NPAIR; p++) {
            u64 ej  = e[p][j];
            u64 dd  = d2[p][j];
            // main epilogue: tot += (in0+in1) * (lj - dd) * e_j
            u64 inn = add2(in0[p], in1[p]);
            u64 w   = fma2(dd, NEG1, ljp);
            tot[p]  = fma2(mul2(inn, w), ej, tot[p]);
            // diagonal correction: totD += (q0 + q1*dd) * e_j^2
            u64 ed2 = mul2(ej, ej);
            u64 cor = fma2(q1p, dd, q0p);
            totD[p] = fma2(cor, ed2, totD[p]);
        }
    }

    #pragma unroll
    for (int p = 0; p < NPAIR; p++) {
        u64 r = mul2(add2(tot[p], totD[p]), e[p][0]);
        float lo, hi; unpack2(r, lo, hi);
        const int mbase = m0 + p * 64 + tx;
        out[n * NTOT + mbase]      = lo;
        out[n * NTOT + mbase + 32] = hi;
    }
}

extern "C" void kernel_launch(void* const* d_in, const int* in_sizes, int n_in,
                              void* d_out, int out_size) {
    const float* x1    = (const float*)d_in[0];
    const float* x2    = (const float*)d_in[1];
    const float* L     = (const float*)d_in[2];
    const float* sigma = (const float*)d_in[3];
    float* out = (float*)d_out;

    dim3 block(BX, BY);
    dim3 grid(NTOT / (BX * 2 * NPAIR), NTOT / BY);   // (8, 256)
    taylor_rbf_fused<<<grid, block>>>(x1, x2, L, sigma, out);
}

// round 6
// speedup vs baseline: 1.2990x; 1.2990x over previous
#include <cuda_runtime.h>

#define D 8
#define NTOT 1024
#define BX 32
#define BY 4
#define NPAIR 2   // 4 outputs per thread as 2 f32x2 pairs

typedef unsigned long long u64;

__device__ __forceinline__ u64 pack2(float lo, float hi) {
    u64 r; asm("mov.b64 %0, {%1,%2};" : "=l"(r) : "f"(lo), "f"(hi)); return r;
}
__device__ __forceinline__ void unpack2(u64 v, float& lo, float& hi) {
    asm("mov.b64 {%0,%1}, %2;" : "=f"(lo), "=f"(hi) : "l"(v));
}
__device__ __forceinline__ u64 fma2(u64 a, u64 b, u64 c) {
    u64 d; asm("fma.rn.f32x2 %0, %1, %2, %3;" : "=l"(d) : "l"(a), "l"(b), "l"(c)); return d;
}
__device__ __forceinline__ u64 mul2(u64 a, u64 b) {
    u64 d; asm("mul.rn.f32x2 %0, %1, %2;" : "=l"(d) : "l"(a), "l"(b)); return d;
}
__device__ __forceinline__ u64 add2(u64 a, u64 b) {
    u64 d; asm("add.rn.f32x2 %0, %1, %2;" : "=l"(d) : "l"(a), "l"(b)); return d;
}
__device__ __forceinline__ float ex2f(float x) {
    float r; asm("ex2.approx.ftz.f32 %0, %1;" : "=f"(r) : "f"(x)); return r;
}
__device__ __forceinline__ float frcp(float x) {
    float r; asm("rcp.approx.ftz.f32 %0, %1;" : "=f"(r) : "f"(x)); return r;
}
__device__ __forceinline__ u64 lo4(float4 v) { return pack2(v.x, v.y); }
__device__ __forceinline__ u64 hi4(float4 v) { return pack2(v.z, v.w); }

// All broadcast constants stored as DUPLICATED pairs: one float4 = two f32x2
// broadcast operands. sigma[0] is pre-folded into AB/An/q0/q1.
// Diagonal correction uses the exact algebraic collapse:
//   poly - tl^2 (1/tl - dd)(l - dd) == 2 - 4*tl*dd
// minblocks=5: R5 showed minblocks=6 (80 regs) spills; 96 regs is spill-free.
__global__ __launch_bounds__(BX * BY, 5)
void taylor_rbf_fused(const float* __restrict__ x1,
                      const float* __restrict__ x2,
                      const float* __restrict__ L,
                      const float* __restrict__ sigma,
                      float* __restrict__ out) {
    __shared__ float4 sAB4[32];   // [j*4+cp]: s0*cf_j*M (dup pairs, c = 2cp, 2cp+1)
    __shared__ float4 sAn4[32];   // [j*4+cp]: -s0*cf_j*M^2
    __shared__ float4 sI4[32];    // [a*4+kp]: inv2[a][k] * (-0.5*log2 e)
    __shared__ float4 sQ4[D];     // [d]: {q0,q0,q1,q1}  q0=2*s0*cf, q1=-4*s0*cf*tl
    __shared__ float2 sLJ[D];     // lij2_j (duplicated)
    __shared__ float2 sx2[D][NPAIR][BX];

    const int tx = threadIdx.x, ty = threadIdx.y;
    const int tid = ty * BX + tx;

    // ---- per-block constant precompute ----
    if (tid < 64) {
        const int c = tid >> 3, j = tid & 7;
        float s0  = sigma[0];
        float Ljc = L[j * D + c];
        float L0c = L[c];
        float i0c = frcp(L0c * L0c);
        float ijc = frcp(Ljc * Ljc);
        float M   = i0c + ijc;
        float l0j = L[j];
        float lij2 = l0j * l0j;
        float cf  = s0 * sigma[j] * frcp(lij2 * lij2);
        float AB  = cf * M;
        float An  = -AB * M;
        const int fo = j * 16 + (c >> 1) * 4 + (c & 1) * 2;
        float* pAB = (float*)sAB4; pAB[fo] = AB; pAB[fo + 1] = AB;
        float* pAn = (float*)sAn4; pAn[fo] = An; pAn[fo + 1] = An;
        // exp table, reusing (a,k) = (c,j)
        float Lak = L[c * D + j];
        float v = -0.72134752044448170368f * frcp(Lak * Lak);
        const int fi = c * 16 + (j >> 1) * 4 + (j & 1) * 2;
        float* pI = (float*)sI4; pI[fi] = v; pI[fi + 1] = v;
    } else if (tid < 72) {
        const int d = tid - 64;
        float s0 = sigma[0];
        float l0 = L[d];
        float lij2 = l0 * l0;
        float Ldd = L[d * D + d];
        float idd = frcp(Ldd * Ldd);
        float i0d = frcp(lij2);
        float tl  = i0d + idd;
        float cf  = s0 * sigma[d] * frcp(lij2 * lij2);
        float q0  = 2.0f * cf;
        float q1  = -4.0f * cf * tl;
        sQ4[d] = make_float4(q0, q0, q1, q1);
        sLJ[d] = make_float2(lij2, lij2);
    }

    // ---- stage x2 tile: (m, m+32) packed into one float2 ----
    const int m0 = blockIdx.x * (BX * 2 * NPAIR);   // 128 m per block
    {
        const int r = tid;
        const int p = r >> 6;
        const int half = (r >> 5) & 1;
        const int t = r & 31;
        const float* src = x2 + (m0 + r) * D;
        #pragma unroll
        for (int k = 0; k < D; k++) {
            float* dst = (float*)&sx2[k][p][t] + half;
            *dst = src[k];
        }
    }

    const int n = blockIdx.y * BY + ty;
    float a1s[D];
    #pragma unroll
    for (int k = 0; k < D; k++) a1s[k] = x1[n * D + k];

    __syncthreads();

    const u64 NEG1 = pack2(-1.0f, -1.0f);

    // diff^2, packed over the m-pair
    u64 d2[NPAIR][D];
    #pragma unroll
    for (int k = 0; k < D; k++) {
        u64 a1 = pack2(a1s[k], a1s[k]);
        #pragma unroll
        for (int p = 0; p < NPAIR; p++) {
            u64 xp = *(const u64*)&sx2[k][p][tx];
            u64 dd = fma2(xp, NEG1, a1);
            d2[p][k] = mul2(dd, dd);
        }
    }

    // e[p][a] = exp(-0.5 * <d2, inv2[a,:]>) via pre-scaled rows + ex2
    u64 e[NPAIR][D];
    #pragma unroll
    for (int a = 0; a < D; a++) {
        float4 q0 = sI4[a * 4 + 0];
        float4 q1 = sI4[a * 4 + 1];
        float4 q2 = sI4[a * 4 + 2];
        float4 q3 = sI4[a * 4 + 3];
        u64 r0 = lo4(q0), r1 = hi4(q0), r2 = lo4(q1), r3 = hi4(q1);
        u64 r4 = lo4(q2), r5 = hi4(q2), r6 = lo4(q3), r7 = hi4(q3);
        #pragma unroll
        for (int p = 0; p < NPAIR; p++) {
            u64 s0 = mul2(d2[p][0], r0);
            u64 s1 = mul2(d2[p][1], r1);
            s0 = fma2(d2[p][2], r2, s0);
            s1 = fma2(d2[p][3], r3, s1);
            s0 = fma2(d2[p][4], r4, s0);
            s1 = fma2(d2[p][5], r5, s1);
            s0 = fma2(d2[p][6], r6, s0);
            s1 = fma2(d2[p][7], r7, s1);
            u64 s = add2(s0, s1);
            float lo, hi; unpack2(s, lo, hi);
            e[p][a] = pack2(ex2f(lo), ex2f(hi));
        }
    }

    u64 tot[NPAIR], totD[NPAIR];
    #pragma unroll
    for (int p = 0; p < NPAIR; p++) { tot[p] = pack2(0.f, 0.f); totD[p] = pack2(0.f, 0.f); }

    // one pass over j: double-sum + collapsed diagonal correction
    #pragma unroll
    for (int j = 0; j < D; j++) {
        u64 in0[NPAIR], in1[NPAIR];
        #pragma unroll
        for (int p = 0; p < NPAIR; p++) { in0[p] = pack2(0.f, 0.f); in1[p] = pack2(0.f, 0.f); }
        #pragma unroll
        for (int cp = 0; cp < 4; cp++) {
            float4 ab = sAB4[j * 4 + cp];
            float4 an = sAn4[j * 4 + cp];
            u64 AB0 = lo4(ab), AB1 = hi4(ab);
            u64 An0 = lo4(an), An1 = hi4(an);
            const int c0 = 2 * cp, c1 = 2 * cp + 1;
            #pragma unroll
            for (int p = 0; p < NPAIR; p++) {
                u64 t0 = fma2(An0, d2[p][c0], AB0);
                in0[p] = fma2(t0, e[p][c0], in0[p]);
                u64 t1 = fma2(An1, d2[p][c1], AB1);
                in1[p] = fma2(t1, e[p][c1], in1[p]);
            }
        }
        u64 ljp = *(const u64*)&sLJ[j];
        float4 qd = sQ4[j];
        u64 q0p = lo4(qd), q1p = hi4(qd);
        #pragma unroll
        for (int p = 0; p < NPAIR; p++) {
            u64 ej  = e[p][j];
            u64 dd  = d2[p][j];
            // main epilogue: tot += (in0+in1) * (lj - dd) * e_j
            u64 inn = add2(in0[p], in1[p]);
            u64 w   = fma2(dd, NEG1, ljp);
            tot[p]  = fma2(mul2(inn, w), ej, tot[p]);
            // diagonal correction: totD += (q0 + q1*dd) * e_j^2
            u64 ed2 = mul2(ej, ej);
            u64 cor = fma2(q1p, dd, q0p);
            totD[p] = fma2(cor, ed2, totD[p]);
        }
    }

    #pragma unroll
    for (int p = 0; p < NPAIR; p++) {
        u64 r = mul2(add2(tot[p], totD[p]), e[p][0]);
        float lo, hi; unpack2(r, lo, hi);
        const int mbase = m0 + p * 64 + tx;
        out[n * NTOT + mbase]      = lo;
        out[n * NTOT + mbase + 32] = hi;
    }
}

extern "C" void kernel_launch(void* const* d_in, const int* in_sizes, int n_in,
                              void* d_out, int out_size) {
    const float* x1    = (const float*)d_in[0];
    const float* x2    = (const float*)d_in[1];
    const float* L     = (const float*)d_in[2];
    const float* sigma = (const float*)d_in[3];
    float* out = (float*)d_out;

    dim3 block(BX, BY);
    dim3 grid(NTOT / (BX * 2 * NPAIR), NTOT / BY);   // (8, 256)
    taylor_rbf_fused<<<grid, block>>>(x1, x2, L, sigma, out);
}